// round 14
// baseline (speedup 1.0000x reference)
#include <cuda_runtime.h>
#include <cuda_bf16.h>
#include <math.h>

#define CIN 32
#define COUT 64

// B-fragments for mma.m16n8k16.bf16, prepacked:
// [tap(125)][kc(2)][ntp(4)][lane(32)] uint4 =
//   (.x = {k0,k0+1}@nt 2ntp, .y = {k0+8,k0+9}@nt 2ntp, .z/.w same @nt 2ntp+1)
// where k0 = 2*(lane&3), n = lane>>2, cin = kc*16 + k.
__device__ uint4 g_bf[125 * 2 * 4 * 32];

__device__ __forceinline__ unsigned pack_bf2(float lo, float hi) {
    unsigned r;
    asm("cvt.rn.bf16x2.f32 %0, %1, %2;" : "=r"(r) : "f"(hi), "f"(lo));
    return r;
}

__global__ void bf_pack_kernel(const float* __restrict__ w) {
    int i = blockIdx.x * blockDim.x + threadIdx.x;
    if (i >= 125 * 2 * 4 * 32) return;
    int lane = i & 31, ntp = (i >> 5) & 3, kc = (i >> 7) & 1, tap = i >> 8;
    int k0 = 2 * (lane & 3), n = lane >> 2;
    int cb = kc * 16;
    int cout0 = ntp * 16 + n, cout1 = cout0 + 8;
#define WV(ci, co) w[((ci) * COUT + (co)) * 125 + tap]
    uint4 o;
    o.x = pack_bf2(WV(cb + k0,     cout0), WV(cb + k0 + 1, cout0));
    o.y = pack_bf2(WV(cb + k0 + 8, cout0), WV(cb + k0 + 9, cout0));
    o.z = pack_bf2(WV(cb + k0,     cout1), WV(cb + k0 + 1, cout1));
    o.w = pack_bf2(WV(cb + k0 + 8, cout1), WV(cb + k0 + 9, cout1));
#undef WV
    g_bf[i] = o;
}

#define MMAB(c, a0, a1, a2, a3, b0, b1)                                          \
    asm("mma.sync.aligned.m16n8k16.row.col.f32.bf16.bf16.f32 "                   \
        "{%0,%1,%2,%3}, {%4,%5,%6,%7}, {%8,%9}, {%0,%1,%2,%3};"                  \
        : "+f"((c)[0]), "+f"((c)[1]), "+f"((c)[2]), "+f"((c)[3])                 \
        : "r"(a0), "r"(a1), "r"(a2), "r"(a3), "r"(b0), "r"(b1))

__device__ __forceinline__ int qoff(int pos) {      // pos in [0,27)
    int qd = pos / 9, qh = (pos / 3) % 3, qw = pos % 3;
    return qd * 25 + qh * 5 + qw;
}

// A-patch layout: xs[w][kc(2)][kb(4)][q(128 pad)] as uint2:
//   .x = bf16x2 of cins (kc*16+2kb, +1)   -> A reg a0/a1
//   .y = bf16x2 of cins (kc*16+2kb+8, +9) -> A reg a2/a3
__global__ __launch_bounds__(128, 2)
void fused_kernel(const float* __restrict__ x,
                  const float* __restrict__ bias,
                  float* __restrict__ out)
{
    __shared__ uint2 xs[2 * 2 * 4 * 128];   // 16 KB
    __shared__ int2  stab[8][27];           // per-class taps: (g_bf uint4-offset, patch q-offset)
    __shared__ float smax[2][4][64];
    __shared__ float ssum[4];

    const int tid  = threadIdx.x;           // 128 threads = 4 warps
    const int wid  = tid >> 5;
    const int lane = tid & 31;
    const int kb   = lane & 3;
    const int rr   = lane >> 2;

    const int b0 = blockIdx.x * 2;          // two windows per block

    // Build per-class tap tables.
    if (tid < 8) {
        const int pd = (tid >> 2) & 1, ph = (tid >> 1) & 1, pw = tid & 1;
        int cnt = 0;
        for (int ia = 0; ia < (pd ? 2 : 3); ++ia) {
            const int kd = pd + 2 * ia, jd = 2 - ia;
            for (int ib = 0; ib < (ph ? 2 : 3); ++ib) {
                const int kh = ph + 2 * ib, jh = 2 - ib;
                for (int ic = 0; ic < (pw ? 2 : 3); ++ic) {
                    const int kw = pw + 2 * ic, jw = 2 - ic;
                    stab[tid][cnt++] = make_int2((kd * 25 + kh * 5 + kw) * 256,
                                                 jd * 25 + jh * 5 + jw);
                }
            }
        }
    }

    // Stage both patches as bf16, zero-fill halo.
    for (int t = tid; t < 8000; t += 128) {
        const int w  = t / 4000;
        const int rm = t - w * 4000;
        const int cin = rm / 125;
        const int q   = rm - cin * 125;
        const int bb  = b0 + w;
        const int n_  = bb / 500;
        const int r_  = bb % 500;
        const int odc = r_ / 100;
        const int ohc = (r_ / 10) % 10;
        const int owc = r_ % 10;
        const int dl = q / 25, hl = (q / 5) % 5, wl = q % 5;
        const int id = 3 * odc - 1 + dl;
        const int ih = 3 * ohc - 1 + hl;
        const int iw = 3 * owc - 1 + wl;
        float v = 0.f;
        if (id >= 0 && ih >= 0 && iw >= 0)
            v = x[(((n_ * CIN + cin) * 16 + id) << 10) + (ih << 5) + iw];
        const int kc  = cin >> 4;
        const int rb  = cin & 15;
        const int par = rb & 1;
        const int cp  = rb >> 1;
        const int kb2 = cp & 3;
        const int j   = cp >> 2;
        const int word = (((w * 2 + kc) * 4 + kb2) * 128 + q) * 2 + j;
        ((__nv_bfloat16*)xs)[word * 2 + par] = __float2bfloat16(v);
    }
    __syncthreads();

    float rmax[2][8][2];
#pragma unroll
    for (int w = 0; w < 2; ++w)
#pragma unroll
        for (int nt = 0; nt < 8; ++nt) { rmax[w][nt][0] = -INFINITY; rmax[w][nt][1] = -INFINITY; }

    // Each warp owns whole classes (BOTH halves) so B loads feed 2x MMAs.
    // Pairs: w0 {0,7}=35 taps, w1 {1,3}=30, w2 {2,5}=30, w3 {4,6}=30.
    const int PAIR[4][2] = {{0, 7}, {1, 3}, {2, 5}, {4, 6}};

    // Position offsets for the 4 m-rows this lane touches:
    //  h0: pos rr, rr+8 (always valid); h1: pos 16+rr (valid), 24+rr (valid iff rr<3)
    const int qo00 = qoff(rr);
    const int qo01 = qoff(rr + 8);
    const int qo10 = qoff(16 + rr);
    const bool v3  = (rr < 3);
    const int qo11 = v3 ? qoff(24 + rr) : 0;

#pragma unroll 1
    for (int s = 0; s < 2; ++s) {
        const int cls = PAIR[wid][s];
        const int ntaps = ((cls & 4) ? 2 : 3) * ((cls & 2) ? 2 : 3) * ((cls & 1) ? 2 : 3);

        float c[2][2][8][4];        // [half][win][ntile][4]
#pragma unroll
        for (int h = 0; h < 2; ++h)
#pragma unroll
            for (int w = 0; w < 2; ++w)
#pragma unroll
                for (int nt = 0; nt < 8; ++nt)
#pragma unroll
                    for (int j = 0; j < 4; ++j) c[h][w][nt][j] = 0.f;

#pragma unroll 1
        for (int t = 0; t < ntaps; ++t) {
            const int2 e = stab[cls][t];
            const uint4* bp = g_bf + e.x + lane;
#pragma unroll
            for (int kc = 0; kc < 2; ++kc) {
                const int a0b = (kc * 4 + kb) * 128 + e.y;
                const int a1b = a0b + 1024;                 // window 1 ((w*2+kc) major)
                const uint2 p000 = xs[a0b + qo00];          // w0 h0 (a0,a2)
                const uint2 p001 = xs[a0b + qo01];          // w0 h0 (a1,a3)
                const uint2 p010 = xs[a0b + qo10];          // w0 h1
                const uint2 p011 = xs[a0b + qo11];
                const uint2 p100 = xs[a1b + qo00];          // w1 h0
                const uint2 p101 = xs[a1b + qo01];
                const uint2 p110 = xs[a1b + qo10];          // w1 h1
                const uint2 p111 = xs[a1b + qo11];
#pragma unroll
                for (int ntp = 0; ntp < 4; ++ntp) {
                    const uint4 B = bp[(kc * 4 + ntp) * 32];
                    MMAB(c[0][0][2 * ntp],     p000.x, p001.x, p000.y, p001.y, B.x, B.y);
                    MMAB(c[0][0][2 * ntp + 1], p000.x, p001.x, p000.y, p001.y, B.z, B.w);
                    MMAB(c[0][1][2 * ntp],     p100.x, p101.x, p100.y, p101.y, B.x, B.y);
                    MMAB(c[0][1][2 * ntp + 1], p100.x, p101.x, p100.y, p101.y, B.z, B.w);
                    MMAB(c[1][0][2 * ntp],     p010.x, p011.x, p010.y, p011.y, B.x, B.y);
                    MMAB(c[1][0][2 * ntp + 1], p010.x, p011.x, p010.y, p011.y, B.z, B.w);
                    MMAB(c[1][1][2 * ntp],     p110.x, p111.x, p110.y, p111.y, B.x, B.y);
                    MMAB(c[1][1][2 * ntp + 1], p110.x, p111.x, p110.y, p111.y, B.z, B.w);
                }
            }
        }

        // fold max-pool (h0 rows all valid; h1 row-pair 2,3 valid iff rr<3)
#pragma unroll
        for (int w = 0; w < 2; ++w)
#pragma unroll
            for (int nt = 0; nt < 8; ++nt) {
                rmax[w][nt][0] = fmaxf(rmax[w][nt][0],
                                       fmaxf(c[0][w][nt][0], c[0][w][nt][2]));
                rmax[w][nt][1] = fmaxf(rmax[w][nt][1],
                                       fmaxf(c[0][w][nt][1], c[0][w][nt][3]));
                rmax[w][nt][0] = fmaxf(rmax[w][nt][0], c[1][w][nt][0]);
                rmax[w][nt][1] = fmaxf(rmax[w][nt][1], c[1][w][nt][1]);
                if (v3) {
                    rmax[w][nt][0] = fmaxf(rmax[w][nt][0], c[1][w][nt][2]);
                    rmax[w][nt][1] = fmaxf(rmax[w][nt][1], c[1][w][nt][3]);
                }
            }
    }

    // reduce max across row-group lanes (same kb)
#pragma unroll
    for (int o = 4; o < 32; o <<= 1)
#pragma unroll
        for (int w = 0; w < 2; ++w)
#pragma unroll
            for (int nt = 0; nt < 8; ++nt) {
                rmax[w][nt][0] = fmaxf(rmax[w][nt][0], __shfl_xor_sync(0xffffffffu, rmax[w][nt][0], o));
                rmax[w][nt][1] = fmaxf(rmax[w][nt][1], __shfl_xor_sync(0xffffffffu, rmax[w][nt][1], o));
            }
    if (rr == 0) {
#pragma unroll
        for (int w = 0; w < 2; ++w)
#pragma unroll
            for (int nt = 0; nt < 8; ++nt) {
                smax[w][wid][nt * 8 + 2 * kb]     = rmax[w][nt][0];
                smax[w][wid][nt * 8 + 2 * kb + 1] = rmax[w][nt][1];
            }
    }
    __syncthreads();

    // tid 0..63 -> window 0, 64..127 -> window 1; cout = tid&63
    {
        const int w    = tid >> 6;
        const int cout = tid & 63;
        float v = fmaxf(fmaxf(smax[w][0][cout], smax[w][1][cout]),
                        fmaxf(smax[w][2][cout], smax[w][3][cout])) + bias[cout];
#pragma unroll
        for (int o = 16; o > 0; o >>= 1)
            v += __shfl_down_sync(0xffffffffu, v, o);
        if (lane == 0) ssum[tid >> 5] = v;
    }
    __syncthreads();
    if (tid == 0) {
        out[b0]     = ssum[0] + ssum[1];
        out[b0 + 1] = ssum[2] + ssum[3];
    }
}

extern "C" void kernel_launch(void* const* d_in, const int* in_sizes, int n_in,
                              void* d_out, int out_size) {
    const float* x    = (const float*)d_in[0];
    const float* w    = (const float*)d_in[1];
    const float* bias = (const float*)d_in[2];
    float* out = (float*)d_out;

    bf_pack_kernel<<<(125 * 2 * 4 * 32 + 255) / 256, 256>>>(w);
    fused_kernel<<<4000, 128>>>(x, bias, out);
}

// round 15
// speedup vs baseline: 1.0002x; 1.0002x over previous
#include <cuda_runtime.h>
#include <cuda_bf16.h>
#include <math.h>

#define CIN 32
#define COUT 64

// B-fragments for mma.m16n8k16.bf16, prepacked:
// [tap(125)][kc(2)][ntp(4)][lane(32)] uint4 =
//   (.x = {k0,k0+1}@nt 2ntp, .y = {k0+8,k0+9}@nt 2ntp, .z/.w same @nt 2ntp+1)
// where k0 = 2*(lane&3), n = lane>>2, cin = kc*16 + k.
__device__ uint4 g_bf[125 * 2 * 4 * 32];

__device__ __forceinline__ unsigned pack_bf2(float lo, float hi) {
    unsigned r;
    asm("cvt.rn.bf16x2.f32 %0, %1, %2;" : "=r"(r) : "f"(hi), "f"(lo));
    return r;
}

__global__ void bf_pack_kernel(const float* __restrict__ w) {
    int i = blockIdx.x * blockDim.x + threadIdx.x;
    if (i >= 125 * 2 * 4 * 32) return;
    int lane = i & 31, ntp = (i >> 5) & 3, kc = (i >> 7) & 1, tap = i >> 8;
    int k0 = 2 * (lane & 3), n = lane >> 2;
    int cb = kc * 16;
    int cout0 = ntp * 16 + n, cout1 = cout0 + 8;
#define WV(ci, co) w[((ci) * COUT + (co)) * 125 + tap]
    uint4 o;
    o.x = pack_bf2(WV(cb + k0,     cout0), WV(cb + k0 + 1, cout0));
    o.y = pack_bf2(WV(cb + k0 + 8, cout0), WV(cb + k0 + 9, cout0));
    o.z = pack_bf2(WV(cb + k0,     cout1), WV(cb + k0 + 1, cout1));
    o.w = pack_bf2(WV(cb + k0 + 8, cout1), WV(cb + k0 + 9, cout1));
#undef WV
    g_bf[i] = o;
}

#define MMAB(c, a0, a1, a2, a3, b0, b1)                                          \
    asm("mma.sync.aligned.m16n8k16.row.col.f32.bf16.bf16.f32 "                   \
        "{%0,%1,%2,%3}, {%4,%5,%6,%7}, {%8,%9}, {%0,%1,%2,%3};"                  \
        : "+f"((c)[0]), "+f"((c)[1]), "+f"((c)[2]), "+f"((c)[3])                 \
        : "r"(a0), "r"(a1), "r"(a2), "r"(a3), "r"(b0), "r"(b1))

__device__ __forceinline__ int qoff(int pos) {      // pos in [0,27)
    int qd = pos / 9, qh = (pos / 3) % 3, qw = pos % 3;
    return qd * 25 + qh * 5 + qw;
}

// A-patch layout: xs[w][kc(2)][kb(4)][q(128 pad)] as uint2:
//   .x = bf16x2 of cins (kc*16+2kb, +1)   -> A reg a0/a1
//   .y = bf16x2 of cins (kc*16+2kb+8, +9) -> A reg a2/a3
__global__ __launch_bounds__(128, 2)
void fused_kernel(const float* __restrict__ x,
                  const float* __restrict__ bias,
                  float* __restrict__ out)
{
    __shared__ uint2 xs[2 * 2 * 4 * 128];   // 16 KB
    __shared__ int2  stab[8][27];           // per-class taps: (g_bf uint4-offset, patch q-offset)
    __shared__ float smax[2][4][64];
    __shared__ float ssum[4];

    const int tid  = threadIdx.x;           // 128 threads = 4 warps
    const int wid  = tid >> 5;
    const int lane = tid & 31;
    const int kb   = lane & 3;
    const int rr   = lane >> 2;

    const int b0 = blockIdx.x * 2;          // two windows per block

    // Build per-class tap tables.
    if (tid < 8) {
        const int pd = (tid >> 2) & 1, ph = (tid >> 1) & 1, pw = tid & 1;
        int cnt = 0;
        for (int ia = 0; ia < (pd ? 2 : 3); ++ia) {
            const int kd = pd + 2 * ia, jd = 2 - ia;
            for (int ib = 0; ib < (ph ? 2 : 3); ++ib) {
                const int kh = ph + 2 * ib, jh = 2 - ib;
                for (int ic = 0; ic < (pw ? 2 : 3); ++ic) {
                    const int kw = pw + 2 * ic, jw = 2 - ic;
                    stab[tid][cnt++] = make_int2((kd * 25 + kh * 5 + kw) * 256,
                                                 jd * 25 + jh * 5 + jw);
                }
            }
        }
    }

    // Stage both patches as bf16, zero-fill halo.
    for (int t = tid; t < 8000; t += 128) {
        const int w  = t / 4000;
        const int rm = t - w * 4000;
        const int cin = rm / 125;
        const int q   = rm - cin * 125;
        const int bb  = b0 + w;
        const int n_  = bb / 500;
        const int r_  = bb % 500;
        const int odc = r_ / 100;
        const int ohc = (r_ / 10) % 10;
        const int owc = r_ % 10;
        const int dl = q / 25, hl = (q / 5) % 5, wl = q % 5;
        const int id = 3 * odc - 1 + dl;
        const int ih = 3 * ohc - 1 + hl;
        const int iw = 3 * owc - 1 + wl;
        float v = 0.f;
        if (id >= 0 && ih >= 0 && iw >= 0)
            v = x[(((n_ * CIN + cin) * 16 + id) << 10) + (ih << 5) + iw];
        const int kc  = cin >> 4;
        const int rb  = cin & 15;
        const int par = rb & 1;
        const int cp  = rb >> 1;
        const int kb2 = cp & 3;
        const int j   = cp >> 2;
        const int word = (((w * 2 + kc) * 4 + kb2) * 128 + q) * 2 + j;
        ((__nv_bfloat16*)xs)[word * 2 + par] = __float2bfloat16(v);
    }
    __syncthreads();

    float rmax[2][8][2];
#pragma unroll
    for (int w = 0; w < 2; ++w)
#pragma unroll
        for (int nt = 0; nt < 8; ++nt) { rmax[w][nt][0] = -INFINITY; rmax[w][nt][1] = -INFINITY; }

    // Each warp owns whole classes (BOTH halves) so B loads feed 2x MMAs.
    // Pairs: w0 {0,7}=35 taps, w1 {1,3}=30, w2 {2,5}=30, w3 {4,6}=30.
    const int PAIR[4][2] = {{0, 7}, {1, 3}, {2, 5}, {4, 6}};

    // Position offsets for the 4 m-rows this lane touches:
    //  h0: pos rr, rr+8 (always valid); h1: pos 16+rr (valid), 24+rr (valid iff rr<3)
    const int qo00 = qoff(rr);
    const int qo01 = qoff(rr + 8);
    const int qo10 = qoff(16 + rr);
    const bool v3  = (rr < 3);
    const int qo11 = v3 ? qoff(24 + rr) : 0;

#pragma unroll 1
    for (int s = 0; s < 2; ++s) {
        const int cls = PAIR[wid][s];
        const int ntaps = ((cls & 4) ? 2 : 3) * ((cls & 2) ? 2 : 3) * ((cls & 1) ? 2 : 3);

        float c[2][2][8][4];        // [half][win][ntile][4]
#pragma unroll
        for (int h = 0; h < 2; ++h)
#pragma unroll
            for (int w = 0; w < 2; ++w)
#pragma unroll
                for (int nt = 0; nt < 8; ++nt)
#pragma unroll
                    for (int j = 0; j < 4; ++j) c[h][w][nt][j] = 0.f;

#pragma unroll 1
        for (int t = 0; t < ntaps; ++t) {
            const int2 e = stab[cls][t];
            const uint4* bp = g_bf + e.x + lane;
#pragma unroll
            for (int kc = 0; kc < 2; ++kc) {
                const int a0b = (kc * 4 + kb) * 128 + e.y;
                const int a1b = a0b + 1024;                 // window 1 ((w*2+kc) major)
                const uint2 p000 = xs[a0b + qo00];          // w0 h0 (a0,a2)
                const uint2 p001 = xs[a0b + qo01];          // w0 h0 (a1,a3)
                const uint2 p010 = xs[a0b + qo10];          // w0 h1
                const uint2 p011 = xs[a0b + qo11];
                const uint2 p100 = xs[a1b + qo00];          // w1 h0
                const uint2 p101 = xs[a1b + qo01];
                const uint2 p110 = xs[a1b + qo10];          // w1 h1
                const uint2 p111 = xs[a1b + qo11];
#pragma unroll
                for (int ntp = 0; ntp < 4; ++ntp) {
                    const uint4 B = bp[(kc * 4 + ntp) * 32];
                    MMAB(c[0][0][2 * ntp],     p000.x, p001.x, p000.y, p001.y, B.x, B.y);
                    MMAB(c[0][0][2 * ntp + 1], p000.x, p001.x, p000.y, p001.y, B.z, B.w);
                    MMAB(c[0][1][2 * ntp],     p100.x, p101.x, p100.y, p101.y, B.x, B.y);
                    MMAB(c[0][1][2 * ntp + 1], p100.x, p101.x, p100.y, p101.y, B.z, B.w);
                    MMAB(c[1][0][2 * ntp],     p010.x, p011.x, p010.y, p011.y, B.x, B.y);
                    MMAB(c[1][0][2 * ntp + 1], p010.x, p011.x, p010.y, p011.y, B.z, B.w);
                    MMAB(c[1][1][2 * ntp],     p110.x, p111.x, p110.y, p111.y, B.x, B.y);
                    MMAB(c[1][1][2 * ntp + 1], p110.x, p111.x, p110.y, p111.y, B.z, B.w);
                }
            }
        }

        // fold max-pool (h0 rows all valid; h1 row-pair 2,3 valid iff rr<3)
#pragma unroll
        for (int w = 0; w < 2; ++w)
#pragma unroll
            for (int nt = 0; nt < 8; ++nt) {
                rmax[w][nt][0] = fmaxf(rmax[w][nt][0],
                                       fmaxf(c[0][w][nt][0], c[0][w][nt][2]));
                rmax[w][nt][1] = fmaxf(rmax[w][nt][1],
                                       fmaxf(c[0][w][nt][1], c[0][w][nt][3]));
                rmax[w][nt][0] = fmaxf(rmax[w][nt][0], c[1][w][nt][0]);
                rmax[w][nt][1] = fmaxf(rmax[w][nt][1], c[1][w][nt][1]);
                if (v3) {
                    rmax[w][nt][0] = fmaxf(rmax[w][nt][0], c[1][w][nt][2]);
                    rmax[w][nt][1] = fmaxf(rmax[w][nt][1], c[1][w][nt][3]);
                }
            }
    }

    // reduce max across row-group lanes (same kb)
#pragma unroll
    for (int o = 4; o < 32; o <<= 1)
#pragma unroll
        for (int w = 0; w < 2; ++w)
#pragma unroll
            for (int nt = 0; nt < 8; ++nt) {
                rmax[w][nt][0] = fmaxf(rmax[w][nt][0], __shfl_xor_sync(0xffffffffu, rmax[w][nt][0], o));
                rmax[w][nt][1] = fmaxf(rmax[w][nt][1], __shfl_xor_sync(0xffffffffu, rmax[w][nt][1], o));
            }
    if (rr == 0) {
#pragma unroll
        for (int w = 0; w < 2; ++w)
#pragma unroll
            for (int nt = 0; nt < 8; ++nt) {
                smax[w][wid][nt * 8 + 2 * kb]     = rmax[w][nt][0];
                smax[w][wid][nt * 8 + 2 * kb + 1] = rmax[w][nt][1];
            }
    }
    __syncthreads();

    // tid 0..63 -> window 0, 64..127 -> window 1; cout = tid&63
    {
        const int w    = tid >> 6;
        const int cout = tid & 63;
        float v = fmaxf(fmaxf(smax[w][0][cout], smax[w][1][cout]),
                        fmaxf(smax[w][2][cout], smax[w][3][cout])) + bias[cout];
#pragma unroll
        for (int o = 16; o > 0; o >>= 1)
            v += __shfl_down_sync(0xffffffffu, v, o);
        if (lane == 0) ssum[tid >> 5] = v;
    }
    __syncthreads();
    if (tid == 0) {
        out[b0]     = ssum[0] + ssum[1];
        out[b0 + 1] = ssum[2] + ssum[3];
    }
}

extern "C" void kernel_launch(void* const* d_in, const int* in_sizes, int n_in,
                              void* d_out, int out_size) {
    const float* x    = (const float*)d_in[0];
    const float* w    = (const float*)d_in[1];
    const float* bias = (const float*)d_in[2];
    float* out = (float*)d_out;

    bf_pack_kernel<<<(125 * 2 * 4 * 32 + 255) / 256, 256>>>(w);
    fused_kernel<<<4000, 128>>>(x, bias, out);
}

// round 16
// speedup vs baseline: 1.0024x; 1.0022x over previous
#include <cuda_runtime.h>
#include <cuda_bf16.h>
#include <math.h>

#define CIN 32
#define COUT 64

// B-fragments for mma.m16n8k16.bf16, prepacked:
// [tap(125)][kc(2)][ntp(4)][lane(32)] uint4 =
//   (.x = {k0,k0+1}@nt 2ntp, .y = {k0+8,k0+9}@nt 2ntp, .z/.w same @nt 2ntp+1)
// where k0 = 2*(lane&3), n = lane>>2, cin = kc*16 + k.
__device__ uint4 g_bf[125 * 2 * 4 * 32];

__device__ __forceinline__ unsigned pack_bf2(float lo, float hi) {
    unsigned r;
    asm("cvt.rn.bf16x2.f32 %0, %1, %2;" : "=r"(r) : "f"(hi), "f"(lo));
    return r;
}

__global__ void bf_pack_kernel(const float* __restrict__ w) {
    int i = blockIdx.x * blockDim.x + threadIdx.x;
    if (i >= 125 * 2 * 4 * 32) return;
    int lane = i & 31, ntp = (i >> 5) & 3, kc = (i >> 7) & 1, tap = i >> 8;
    int k0 = 2 * (lane & 3), n = lane >> 2;
    int cb = kc * 16;
    int cout0 = ntp * 16 + n, cout1 = cout0 + 8;
#define WV(ci, co) w[((ci) * COUT + (co)) * 125 + tap]
    uint4 o;
    o.x = pack_bf2(WV(cb + k0,     cout0), WV(cb + k0 + 1, cout0));
    o.y = pack_bf2(WV(cb + k0 + 8, cout0), WV(cb + k0 + 9, cout0));
    o.z = pack_bf2(WV(cb + k0,     cout1), WV(cb + k0 + 1, cout1));
    o.w = pack_bf2(WV(cb + k0 + 8, cout1), WV(cb + k0 + 9, cout1));
#undef WV
    g_bf[i] = o;
}

#define MMAB(c, a0, a1, a2, a3, b0, b1)                                          \
    asm("mma.sync.aligned.m16n8k16.row.col.f32.bf16.bf16.f32 "                   \
        "{%0,%1,%2,%3}, {%4,%5,%6,%7}, {%8,%9}, {%0,%1,%2,%3};"                  \
        : "+f"((c)[0]), "+f"((c)[1]), "+f"((c)[2]), "+f"((c)[3])                 \
        : "r"(a0), "r"(a1), "r"(a2), "r"(a3), "r"(b0), "r"(b1))

__device__ __forceinline__ int qoff(int pos) {      // pos in [0,27)
    int qd = pos / 9, qh = (pos / 3) % 3, qw = pos % 3;
    return qd * 25 + qh * 5 + qw;
}

// A-patch layout: xs[w][kc(2)][kb(4)][q(128 pad)] as uint2:
//   .x = bf16x2 of cins (kc*16+2kb, +1)   -> A reg a0/a1
//   .y = bf16x2 of cins (kc*16+2kb+8, +9) -> A reg a2/a3
__global__ __launch_bounds__(128, 2)
void fused_kernel(const float* __restrict__ x,
                  const float* __restrict__ bias,
                  float* __restrict__ out)
{
    __shared__ uint2 xs[2 * 2 * 4 * 128];   // 16 KB
    __shared__ int2  stab[8][27];           // per-class taps: (g_bf uint4-offset, patch q-offset)
    __shared__ float smax[2][4][64];
    __shared__ float ssum[4];

    const int tid  = threadIdx.x;           // 128 threads = 4 warps
    const int wid  = tid >> 5;
    const int lane = tid & 31;
    const int kb   = lane & 3;
    const int rr   = lane >> 2;

    const int b0 = blockIdx.x * 2;          // two windows per block

    // Build per-class tap tables.
    if (tid < 8) {
        const int pd = (tid >> 2) & 1, ph = (tid >> 1) & 1, pw = tid & 1;
        int cnt = 0;
        for (int ia = 0; ia < (pd ? 2 : 3); ++ia) {
            const int kd = pd + 2 * ia, jd = 2 - ia;
            for (int ib = 0; ib < (ph ? 2 : 3); ++ib) {
                const int kh = ph + 2 * ib, jh = 2 - ib;
                for (int ic = 0; ic < (pw ? 2 : 3); ++ic) {
                    const int kw = pw + 2 * ic, jw = 2 - ic;
                    stab[tid][cnt++] = make_int2((kd * 25 + kh * 5 + kw) * 256,
                                                 jd * 25 + jh * 5 + jw);
                }
            }
        }
    }

    // Stage both patches as bf16, zero-fill halo.
    for (int t = tid; t < 8000; t += 128) {
        const int w  = t / 4000;
        const int rm = t - w * 4000;
        const int cin = rm / 125;
        const int q   = rm - cin * 125;
        const int bb  = b0 + w;
        const int n_  = bb / 500;
        const int r_  = bb % 500;
        const int odc = r_ / 100;
        const int ohc = (r_ / 10) % 10;
        const int owc = r_ % 10;
        const int dl = q / 25, hl = (q / 5) % 5, wl = q % 5;
        const int id = 3 * odc - 1 + dl;
        const int ih = 3 * ohc - 1 + hl;
        const int iw = 3 * owc - 1 + wl;
        float v = 0.f;
        if (id >= 0 && ih >= 0 && iw >= 0)
            v = x[(((n_ * CIN + cin) * 16 + id) << 10) + (ih << 5) + iw];
        const int kc  = cin >> 4;
        const int rb  = cin & 15;
        const int par = rb & 1;
        const int cp  = rb >> 1;
        const int kb2 = cp & 3;
        const int j   = cp >> 2;
        const int word = (((w * 2 + kc) * 4 + kb2) * 128 + q) * 2 + j;
        ((__nv_bfloat16*)xs)[word * 2 + par] = __float2bfloat16(v);
    }
    __syncthreads();

    float rmax[2][8][2];
#pragma unroll
    for (int w = 0; w < 2; ++w)
#pragma unroll
        for (int nt = 0; nt < 8; ++nt) { rmax[w][nt][0] = -INFINITY; rmax[w][nt][1] = -INFINITY; }

    // Each warp owns whole classes (BOTH halves) so B loads feed 2x MMAs.
    // Pairs: w0 {0,7}=35 taps, w1 {1,3}=30, w2 {2,5}=30, w3 {4,6}=30.
    const int PAIR[4][2] = {{0, 7}, {1, 3}, {2, 5}, {4, 6}};

    // Position offsets for the 4 m-rows this lane touches:
    //  h0: pos rr, rr+8 (always valid); h1: pos 16+rr (valid), 24+rr (valid iff rr<3)
    const int qo00 = qoff(rr);
    const int qo01 = qoff(rr + 8);
    const int qo10 = qoff(16 + rr);
    const bool v3  = (rr < 3);
    const int qo11 = v3 ? qoff(24 + rr) : 0;

#pragma unroll 1
    for (int s = 0; s < 2; ++s) {
        const int cls = PAIR[wid][s];
        const int ntaps = ((cls & 4) ? 2 : 3) * ((cls & 2) ? 2 : 3) * ((cls & 1) ? 2 : 3);

        float c[2][2][8][4];        // [half][win][ntile][4]
#pragma unroll
        for (int h = 0; h < 2; ++h)
#pragma unroll
            for (int w = 0; w < 2; ++w)
#pragma unroll
                for (int nt = 0; nt < 8; ++nt)
#pragma unroll
                    for (int j = 0; j < 4; ++j) c[h][w][nt][j] = 0.f;

#pragma unroll 1
        for (int t = 0; t < ntaps; ++t) {
            const int2 e = stab[cls][t];
            const uint4* bp = g_bf + e.x + lane;
#pragma unroll
            for (int kc = 0; kc < 2; ++kc) {
                const int a0b = (kc * 4 + kb) * 128 + e.y;
                const int a1b = a0b + 1024;                 // window 1 ((w*2+kc) major)
                const uint2 p000 = xs[a0b + qo00];          // w0 h0 (a0,a2)
                const uint2 p001 = xs[a0b + qo01];          // w0 h0 (a1,a3)
                const uint2 p010 = xs[a0b + qo10];          // w0 h1
                const uint2 p011 = xs[a0b + qo11];
                const uint2 p100 = xs[a1b + qo00];          // w1 h0
                const uint2 p101 = xs[a1b + qo01];
                const uint2 p110 = xs[a1b + qo10];          // w1 h1
                const uint2 p111 = xs[a1b + qo11];
#pragma unroll
                for (int ntp = 0; ntp < 4; ++ntp) {
                    const uint4 B = bp[(kc * 4 + ntp) * 32];
                    MMAB(c[0][0][2 * ntp],     p000.x, p001.x, p000.y, p001.y, B.x, B.y);
                    MMAB(c[0][0][2 * ntp + 1], p000.x, p001.x, p000.y, p001.y, B.z, B.w);
                    MMAB(c[0][1][2 * ntp],     p100.x, p101.x, p100.y, p101.y, B.x, B.y);
                    MMAB(c[0][1][2 * ntp + 1], p100.x, p101.x, p100.y, p101.y, B.z, B.w);
                    MMAB(c[1][0][2 * ntp],     p010.x, p011.x, p010.y, p011.y, B.x, B.y);
                    MMAB(c[1][0][2 * ntp + 1], p010.x, p011.x, p010.y, p011.y, B.z, B.w);
                    MMAB(c[1][1][2 * ntp],     p110.x, p111.x, p110.y, p111.y, B.x, B.y);
                    MMAB(c[1][1][2 * ntp + 1], p110.x, p111.x, p110.y, p111.y, B.z, B.w);
                }
            }
        }

        // fold max-pool (h0 rows all valid; h1 row-pair 2,3 valid iff rr<3)
#pragma unroll
        for (int w = 0; w < 2; ++w)
#pragma unroll
            for (int nt = 0; nt < 8; ++nt) {
                rmax[w][nt][0] = fmaxf(rmax[w][nt][0],
                                       fmaxf(c[0][w][nt][0], c[0][w][nt][2]));
                rmax[w][nt][1] = fmaxf(rmax[w][nt][1],
                                       fmaxf(c[0][w][nt][1], c[0][w][nt][3]));
                rmax[w][nt][0] = fmaxf(rmax[w][nt][0], c[1][w][nt][0]);
                rmax[w][nt][1] = fmaxf(rmax[w][nt][1], c[1][w][nt][1]);
                if (v3) {
                    rmax[w][nt][0] = fmaxf(rmax[w][nt][0], c[1][w][nt][2]);
                    rmax[w][nt][1] = fmaxf(rmax[w][nt][1], c[1][w][nt][3]);
                }
            }
    }

    // reduce max across row-group lanes (same kb)
#pragma unroll
    for (int o = 4; o < 32; o <<= 1)
#pragma unroll
        for (int w = 0; w < 2; ++w)
#pragma unroll
            for (int nt = 0; nt < 8; ++nt) {
                rmax[w][nt][0] = fmaxf(rmax[w][nt][0], __shfl_xor_sync(0xffffffffu, rmax[w][nt][0], o));
                rmax[w][nt][1] = fmaxf(rmax[w][nt][1], __shfl_xor_sync(0xffffffffu, rmax[w][nt][1], o));
            }
    if (rr == 0) {
#pragma unroll
        for (int w = 0; w < 2; ++w)
#pragma unroll
            for (int nt = 0; nt < 8; ++nt) {
                smax[w][wid][nt * 8 + 2 * kb]     = rmax[w][nt][0];
                smax[w][wid][nt * 8 + 2 * kb + 1] = rmax[w][nt][1];
            }
    }
    __syncthreads();

    // tid 0..63 -> window 0, 64..127 -> window 1; cout = tid&63
    {
        const int w    = tid >> 6;
        const int cout = tid & 63;
        float v = fmaxf(fmaxf(smax[w][0][cout], smax[w][1][cout]),
                        fmaxf(smax[w][2][cout], smax[w][3][cout])) + bias[cout];
#pragma unroll
        for (int o = 16; o > 0; o >>= 1)
            v += __shfl_down_sync(0xffffffffu, v, o);
        if (lane == 0) ssum[tid >> 5] = v;
    }
    __syncthreads();
    if (tid == 0) {
        out[b0]     = ssum[0] + ssum[1];
        out[b0 + 1] = ssum[2] + ssum[3];
    }
}

extern "C" void kernel_launch(void* const* d_in, const int* in_sizes, int n_in,
                              void* d_out, int out_size) {
    const float* x    = (const float*)d_in[0];
    const float* w    = (const float*)d_in[1];
    const float* bias = (const float*)d_in[2];
    float* out = (float*)d_out;

    bf_pack_kernel<<<(125 * 2 * 4 * 32 + 255) / 256, 256>>>(w);
    fused_kernel<<<4000, 128>>>(x, bias, out);
}

// round 17
// speedup vs baseline: 1.0034x; 1.0010x over previous
#include <cuda_runtime.h>
#include <cuda_bf16.h>
#include <math.h>

#define CIN 32
#define COUT 64

// B-fragments for mma.m16n8k16.bf16, prepacked:
// [tap(125)][kc(2)][ntp(4)][lane(32)] uint4 =
//   (.x = {k0,k0+1}@nt 2ntp, .y = {k0+8,k0+9}@nt 2ntp, .z/.w same @nt 2ntp+1)
// where k0 = 2*(lane&3), n = lane>>2, cin = kc*16 + k.
__device__ uint4 g_bf[125 * 2 * 4 * 32];

__device__ __forceinline__ unsigned pack_bf2(float lo, float hi) {
    unsigned r;
    asm("cvt.rn.bf16x2.f32 %0, %1, %2;" : "=r"(r) : "f"(hi), "f"(lo));
    return r;
}

__global__ void bf_pack_kernel(const float* __restrict__ w) {
    int i = blockIdx.x * blockDim.x + threadIdx.x;
    if (i >= 125 * 2 * 4 * 32) return;
    int lane = i & 31, ntp = (i >> 5) & 3, kc = (i >> 7) & 1, tap = i >> 8;
    int k0 = 2 * (lane & 3), n = lane >> 2;
    int cb = kc * 16;
    int cout0 = ntp * 16 + n, cout1 = cout0 + 8;
#define WV(ci, co) w[((ci) * COUT + (co)) * 125 + tap]
    uint4 o;
    o.x = pack_bf2(WV(cb + k0,     cout0), WV(cb + k0 + 1, cout0));
    o.y = pack_bf2(WV(cb + k0 + 8, cout0), WV(cb + k0 + 9, cout0));
    o.z = pack_bf2(WV(cb + k0,     cout1), WV(cb + k0 + 1, cout1));
    o.w = pack_bf2(WV(cb + k0 + 8, cout1), WV(cb + k0 + 9, cout1));
#undef WV
    g_bf[i] = o;
}

#define MMAB(c, a0, a1, a2, a3, b0, b1)                                          \
    asm("mma.sync.aligned.m16n8k16.row.col.f32.bf16.bf16.f32 "                   \
        "{%0,%1,%2,%3}, {%4,%5,%6,%7}, {%8,%9}, {%0,%1,%2,%3};"                  \
        : "+f"((c)[0]), "+f"((c)[1]), "+f"((c)[2]), "+f"((c)[3])                 \
        : "r"(a0), "r"(a1), "r"(a2), "r"(a3), "r"(b0), "r"(b1))

__device__ __forceinline__ int qoff(int pos) {      // pos in [0,27)
    int qd = pos / 9, qh = (pos / 3) % 3, qw = pos % 3;
    return qd * 25 + qh * 5 + qw;
}

// A-patch layout: xs[w][kc(2)][kb(4)][q(128 pad)] as uint2:
//   .x = bf16x2 of cins (kc*16+2kb, +1)   -> A reg a0/a1
//   .y = bf16x2 of cins (kc*16+2kb+8, +9) -> A reg a2/a3
__global__ __launch_bounds__(128, 2)
void fused_kernel(const float* __restrict__ x,
                  const float* __restrict__ bias,
                  float* __restrict__ out)
{
    __shared__ uint2 xs[2 * 2 * 4 * 128];   // 16 KB
    __shared__ int2  stab[8][27];           // per-class taps: (g_bf uint4-offset, patch q-offset)
    __shared__ float smax[2][4][64];
    __shared__ float ssum[4];

    const int tid  = threadIdx.x;           // 128 threads = 4 warps
    const int wid  = tid >> 5;
    const int lane = tid & 31;
    const int kb   = lane & 3;
    const int rr   = lane >> 2;

    const int b0 = blockIdx.x * 2;          // two windows per block

    // Build per-class tap tables.
    if (tid < 8) {
        const int pd = (tid >> 2) & 1, ph = (tid >> 1) & 1, pw = tid & 1;
        int cnt = 0;
        for (int ia = 0; ia < (pd ? 2 : 3); ++ia) {
            const int kd = pd + 2 * ia, jd = 2 - ia;
            for (int ib = 0; ib < (ph ? 2 : 3); ++ib) {
                const int kh = ph + 2 * ib, jh = 2 - ib;
                for (int ic = 0; ic < (pw ? 2 : 3); ++ic) {
                    const int kw = pw + 2 * ic, jw = 2 - ic;
                    stab[tid][cnt++] = make_int2((kd * 25 + kh * 5 + kw) * 256,
                                                 jd * 25 + jh * 5 + jw);
                }
            }
        }
    }

    // Stage both patches as bf16, zero-fill halo.
    for (int t = tid; t < 8000; t += 128) {
        const int w  = t / 4000;
        const int rm = t - w * 4000;
        const int cin = rm / 125;
        const int q   = rm - cin * 125;
        const int bb  = b0 + w;
        const int n_  = bb / 500;
        const int r_  = bb % 500;
        const int odc = r_ / 100;
        const int ohc = (r_ / 10) % 10;
        const int owc = r_ % 10;
        const int dl = q / 25, hl = (q / 5) % 5, wl = q % 5;
        const int id = 3 * odc - 1 + dl;
        const int ih = 3 * ohc - 1 + hl;
        const int iw = 3 * owc - 1 + wl;
        float v = 0.f;
        if (id >= 0 && ih >= 0 && iw >= 0)
            v = x[(((n_ * CIN + cin) * 16 + id) << 10) + (ih << 5) + iw];
        const int kc  = cin >> 4;
        const int rb  = cin & 15;
        const int par = rb & 1;
        const int cp  = rb >> 1;
        const int kb2 = cp & 3;
        const int j   = cp >> 2;
        const int word = (((w * 2 + kc) * 4 + kb2) * 128 + q) * 2 + j;
        ((__nv_bfloat16*)xs)[word * 2 + par] = __float2bfloat16(v);
    }
    __syncthreads();

    float rmax[2][8][2];
#pragma unroll
    for (int w = 0; w < 2; ++w)
#pragma unroll
        for (int nt = 0; nt < 8; ++nt) { rmax[w][nt][0] = -INFINITY; rmax[w][nt][1] = -INFINITY; }

    // Each warp owns whole classes (BOTH halves) so B loads feed 2x MMAs.
    // Pairs: w0 {0,7}=35 taps, w1 {1,3}=30, w2 {2,5}=30, w3 {4,6}=30.
    const int PAIR[4][2] = {{0, 7}, {1, 3}, {2, 5}, {4, 6}};

    // Position offsets for the 4 m-rows this lane touches:
    //  h0: pos rr, rr+8 (always valid); h1: pos 16+rr (valid), 24+rr (valid iff rr<3)
    const int qo00 = qoff(rr);
    const int qo01 = qoff(rr + 8);
    const int qo10 = qoff(16 + rr);
    const bool v3  = (rr < 3);
    const int qo11 = v3 ? qoff(24 + rr) : 0;

#pragma unroll 1
    for (int s = 0; s < 2; ++s) {
        const int cls = PAIR[wid][s];
        const int ntaps = ((cls & 4) ? 2 : 3) * ((cls & 2) ? 2 : 3) * ((cls & 1) ? 2 : 3);

        float c[2][2][8][4];        // [half][win][ntile][4]
#pragma unroll
        for (int h = 0; h < 2; ++h)
#pragma unroll
            for (int w = 0; w < 2; ++w)
#pragma unroll
                for (int nt = 0; nt < 8; ++nt)
#pragma unroll
                    for (int j = 0; j < 4; ++j) c[h][w][nt][j] = 0.f;

#pragma unroll 1
        for (int t = 0; t < ntaps; ++t) {
            const int2 e = stab[cls][t];
            const uint4* bp = g_bf + e.x + lane;
#pragma unroll
            for (int kc = 0; kc < 2; ++kc) {
                const int a0b = (kc * 4 + kb) * 128 + e.y;
                const int a1b = a0b + 1024;                 // window 1 ((w*2+kc) major)
                const uint2 p000 = xs[a0b + qo00];          // w0 h0 (a0,a2)
                const uint2 p001 = xs[a0b + qo01];          // w0 h0 (a1,a3)
                const uint2 p010 = xs[a0b + qo10];          // w0 h1
                const uint2 p011 = xs[a0b + qo11];
                const uint2 p100 = xs[a1b + qo00];          // w1 h0
                const uint2 p101 = xs[a1b + qo01];
                const uint2 p110 = xs[a1b + qo10];          // w1 h1
                const uint2 p111 = xs[a1b + qo11];
#pragma unroll
                for (int ntp = 0; ntp < 4; ++ntp) {
                    const uint4 B = bp[(kc * 4 + ntp) * 32];
                    MMAB(c[0][0][2 * ntp],     p000.x, p001.x, p000.y, p001.y, B.x, B.y);
                    MMAB(c[0][0][2 * ntp + 1], p000.x, p001.x, p000.y, p001.y, B.z, B.w);
                    MMAB(c[0][1][2 * ntp],     p100.x, p101.x, p100.y, p101.y, B.x, B.y);
                    MMAB(c[0][1][2 * ntp + 1], p100.x, p101.x, p100.y, p101.y, B.z, B.w);
                    MMAB(c[1][0][2 * ntp],     p010.x, p011.x, p010.y, p011.y, B.x, B.y);
                    MMAB(c[1][0][2 * ntp + 1], p010.x, p011.x, p010.y, p011.y, B.z, B.w);
                    MMAB(c[1][1][2 * ntp],     p110.x, p111.x, p110.y, p111.y, B.x, B.y);
                    MMAB(c[1][1][2 * ntp + 1], p110.x, p111.x, p110.y, p111.y, B.z, B.w);
                }
            }
        }

        // fold max-pool (h0 rows all valid; h1 row-pair 2,3 valid iff rr<3)
#pragma unroll
        for (int w = 0; w < 2; ++w)
#pragma unroll
            for (int nt = 0; nt < 8; ++nt) {
                rmax[w][nt][0] = fmaxf(rmax[w][nt][0],
                                       fmaxf(c[0][w][nt][0], c[0][w][nt][2]));
                rmax[w][nt][1] = fmaxf(rmax[w][nt][1],
                                       fmaxf(c[0][w][nt][1], c[0][w][nt][3]));
                rmax[w][nt][0] = fmaxf(rmax[w][nt][0], c[1][w][nt][0]);
                rmax[w][nt][1] = fmaxf(rmax[w][nt][1], c[1][w][nt][1]);
                if (v3) {
                    rmax[w][nt][0] = fmaxf(rmax[w][nt][0], c[1][w][nt][2]);
                    rmax[w][nt][1] = fmaxf(rmax[w][nt][1], c[1][w][nt][3]);
                }
            }
    }

    // reduce max across row-group lanes (same kb)
#pragma unroll
    for (int o = 4; o < 32; o <<= 1)
#pragma unroll
        for (int w = 0; w < 2; ++w)
#pragma unroll
            for (int nt = 0; nt < 8; ++nt) {
                rmax[w][nt][0] = fmaxf(rmax[w][nt][0], __shfl_xor_sync(0xffffffffu, rmax[w][nt][0], o));
                rmax[w][nt][1] = fmaxf(rmax[w][nt][1], __shfl_xor_sync(0xffffffffu, rmax[w][nt][1], o));
            }
    if (rr == 0) {
#pragma unroll
        for (int w = 0; w < 2; ++w)
#pragma unroll
            for (int nt = 0; nt < 8; ++nt) {
                smax[w][wid][nt * 8 + 2 * kb]     = rmax[w][nt][0];
                smax[w][wid][nt * 8 + 2 * kb + 1] = rmax[w][nt][1];
            }
    }
    __syncthreads();

    // tid 0..63 -> window 0, 64..127 -> window 1; cout = tid&63
    {
        const int w    = tid >> 6;
        const int cout = tid & 63;
        float v = fmaxf(fmaxf(smax[w][0][cout], smax[w][1][cout]),
                        fmaxf(smax[w][2][cout], smax[w][3][cout])) + bias[cout];
#pragma unroll
        for (int o = 16; o > 0; o >>= 1)
            v += __shfl_down_sync(0xffffffffu, v, o);
        if (lane == 0) ssum[tid >> 5] = v;
    }
    __syncthreads();
    if (tid == 0) {
        out[b0]     = ssum[0] + ssum[1];
        out[b0 + 1] = ssum[2] + ssum[3];
    }
}

extern "C" void kernel_launch(void* const* d_in, const int* in_sizes, int n_in,
                              void* d_out, int out_size) {
    const float* x    = (const float*)d_in[0];
    const float* w    = (const float*)d_in[1];
    const float* bias = (const float*)d_in[2];
    float* out = (float*)d_out;

    bf_pack_kernel<<<(125 * 2 * 4 * 32 + 255) / 256, 256>>>(w);
    fused_kernel<<<4000, 128>>>(x, bias, out);
}